// round 5
// baseline (speedup 1.0000x reference)
#include <cuda_runtime.h>
#include <cuda_bf16.h>

#define D_DIM 128
#define MAX_NODES 50000
#define MAX_EDGES 800000
#define AS_STRIDE 132
#define SCAN_THREADS 1024

__device__ float g_agg[MAX_NODES * D_DIM];
__device__ float g_Wt[D_DIM * D_DIM];       // Wt[k][j] = W[j][k]
__device__ int   g_count[MAX_NODES];
__device__ int   g_offset[MAX_NODES + 1];
__device__ int   g_cursor[MAX_NODES];
__device__ int   g_elist[MAX_EDGES];        // src ids grouped by dst
__device__ int   g_idx64;

// ---------------------------------------------------------------------------
// Detect int64 vs int32 indices (JAX without x64 silently emits i32).
// ---------------------------------------------------------------------------
__global__ void detect_kernel(const void* srcp, int n_edges, int n_nodes) {
    if (threadIdx.x == 0) g_idx64 = 1;
    __syncthreads();
    int n = n_edges < 64 ? n_edges : 64;
    if (threadIdx.x < n) {
        long long v = ((const long long*)srcp)[threadIdx.x];
        if (v < 0 || v >= (long long)n_nodes) g_idx64 = 0;
    }
}

__global__ void zero_count_kernel(int n_nodes) {
    int i = blockIdx.x * blockDim.x + threadIdx.x;
    if (i < n_nodes) g_count[i] = 0;
}

// ---------------------------------------------------------------------------
// Histogram of dst degrees (RED.ADD, spread addresses).
// ---------------------------------------------------------------------------
__global__ void hist_kernel(const void* __restrict__ dstp, int n_edges) {
    int e = blockIdx.x * blockDim.x + threadIdx.x;
    if (e >= n_edges) return;
    int d = g_idx64 ? (int)((const long long*)dstp)[e]
                    : ((const int*)dstp)[e];
    atomicAdd(&g_count[d], 1);
}

// ---------------------------------------------------------------------------
// Single-block exclusive scan of g_count -> g_offset / g_cursor.
// ---------------------------------------------------------------------------
__global__ void scan_kernel(int n_nodes) {
    __shared__ int s[SCAN_THREADS];
    int t = threadIdx.x;
    int chunk = (n_nodes + SCAN_THREADS - 1) / SCAN_THREADS;
    int beg = t * chunk;
    int end = beg + chunk; if (end > n_nodes) end = n_nodes;

    int sum = 0;
    for (int i = beg; i < end; i++) sum += g_count[i];
    s[t] = sum;
    __syncthreads();
    // Hillis-Steele inclusive scan
    for (int off = 1; off < SCAN_THREADS; off <<= 1) {
        int v = (t >= off) ? s[t - off] : 0;
        __syncthreads();
        s[t] += v;
        __syncthreads();
    }
    int run = (t == 0) ? 0 : s[t - 1];   // exclusive prefix of this chunk
    for (int i = beg; i < end; i++) {
        g_offset[i] = run;
        g_cursor[i] = run;
        run += g_count[i];
    }
    if (t == SCAN_THREADS - 1) g_offset[n_nodes] = s[SCAN_THREADS - 1];
}

// ---------------------------------------------------------------------------
// Placement: bucket src ids by dst into g_elist.
// ---------------------------------------------------------------------------
__global__ void place_kernel(const void* __restrict__ srcp,
                             const void* __restrict__ dstp, int n_edges) {
    int e = blockIdx.x * blockDim.x + threadIdx.x;
    if (e >= n_edges) return;
    int s, d;
    if (g_idx64) {
        s = (int)((const long long*)srcp)[e];
        d = (int)((const long long*)dstp)[e];
    } else {
        s = ((const int*)srcp)[e];
        d = ((const int*)dstp)[e];
    }
    int pos = atomicAdd(&g_cursor[d], 1);
    g_elist[pos] = s;
}

// ---------------------------------------------------------------------------
// Gather: one warp per node, register accumulation (atomic-free).
// Lane owns one float4 of the 128-float row. Unroll-4 over in-edges -> MLP=4.
// Writes every row (zero-degree nodes included) so no separate zero pass.
// ---------------------------------------------------------------------------
__global__ void gather_kernel(const float* __restrict__ x, int n_nodes) {
    int warps_per_block = blockDim.x >> 5;
    int node = blockIdx.x * warps_per_block + (threadIdx.x >> 5);
    if (node >= n_nodes) return;
    int lane = threadIdx.x & 31;

    int beg = g_offset[node];
    int end = g_offset[node + 1];

    float4 acc = make_float4(0.f, 0.f, 0.f, 0.f);
    int i = beg;
    for (; i + 4 <= end; i += 4) {
        int s0 = __ldg(&g_elist[i + 0]);
        int s1 = __ldg(&g_elist[i + 1]);
        int s2 = __ldg(&g_elist[i + 2]);
        int s3 = __ldg(&g_elist[i + 3]);
        float4 v0 = ((const float4*)(x + (long long)s0 * D_DIM))[lane];
        float4 v1 = ((const float4*)(x + (long long)s1 * D_DIM))[lane];
        float4 v2 = ((const float4*)(x + (long long)s2 * D_DIM))[lane];
        float4 v3 = ((const float4*)(x + (long long)s3 * D_DIM))[lane];
        acc.x += (v0.x + v1.x) + (v2.x + v3.x);
        acc.y += (v0.y + v1.y) + (v2.y + v3.y);
        acc.z += (v0.z + v1.z) + (v2.z + v3.z);
        acc.w += (v0.w + v1.w) + (v2.w + v3.w);
    }
    for (; i < end; i++) {
        int s0 = __ldg(&g_elist[i]);
        float4 v0 = ((const float4*)(x + (long long)s0 * D_DIM))[lane];
        acc.x += v0.x; acc.y += v0.y; acc.z += v0.z; acc.w += v0.w;
    }
    ((float4*)(g_agg + (long long)node * D_DIM))[lane] = acc;
}

// ---------------------------------------------------------------------------
// Transpose W [j][k] -> g_Wt [k][j] (32x33 smem tile). grid (4,4), block (32,8).
// ---------------------------------------------------------------------------
__global__ void transpose_W_kernel(const float* __restrict__ W) {
    __shared__ float t[32][33];
    int x = blockIdx.x * 32 + threadIdx.x;
    #pragma unroll
    for (int i = threadIdx.y; i < 32; i += 8)
        t[i][threadIdx.x] = W[(blockIdx.y * 32 + i) * D_DIM + x];
    __syncthreads();
    int xo = blockIdx.y * 32 + threadIdx.x;
    #pragma unroll
    for (int i = threadIdx.y; i < 32; i += 8)
        g_Wt[(blockIdx.x * 32 + i) * D_DIM + xo] = t[threadIdx.x][i];
}

// ---------------------------------------------------------------------------
// GEMM + ReLU + residual. 128x128 block tile, 256 threads, 8x8 per thread.
// ---------------------------------------------------------------------------
__global__ __launch_bounds__(256, 1)
void gemm_kernel(const float* __restrict__ x,
                 float* __restrict__ out,
                 int n_nodes) {
    extern __shared__ float smem[];
    float* Ws = smem;                    // [128][128]
    float* As = smem + D_DIM * D_DIM;    // [128][AS_STRIDE]

    int tid = threadIdx.x;
    int row0 = blockIdx.x * 128;

    #pragma unroll
    for (int i = tid; i < D_DIM * D_DIM; i += 256)
        Ws[i] = g_Wt[i];

    #pragma unroll
    for (int i = tid; i < 128 * D_DIM; i += 256) {
        int r = i >> 7;
        int k = i & 127;
        int row = row0 + r;
        float v = (row < n_nodes) ? g_agg[(long long)row * D_DIM + k] : 0.f;
        As[k * AS_STRIDE + r] = v;
    }
    __syncthreads();

    int tx = tid & 15;
    int ty = tid >> 4;
    int r0 = ty * 8;
    int c0 = tx * 8;

    float acc[8][8];
    #pragma unroll
    for (int a = 0; a < 8; a++)
        #pragma unroll
        for (int b = 0; b < 8; b++) acc[a][b] = 0.f;

    #pragma unroll 4
    for (int k = 0; k < D_DIM; k++) {
        float4 a0 = *(const float4*)&As[k * AS_STRIDE + r0];
        float4 a1 = *(const float4*)&As[k * AS_STRIDE + r0 + 4];
        float4 w0 = *(const float4*)&Ws[k * D_DIM + c0];
        float4 w1 = *(const float4*)&Ws[k * D_DIM + c0 + 4];
        float av[8] = {a0.x, a0.y, a0.z, a0.w, a1.x, a1.y, a1.z, a1.w};
        float wv[8] = {w0.x, w0.y, w0.z, w0.w, w1.x, w1.y, w1.z, w1.w};
        #pragma unroll
        for (int a = 0; a < 8; a++)
            #pragma unroll
            for (int b = 0; b < 8; b++)
                acc[a][b] = fmaf(av[a], wv[b], acc[a][b]);
    }

    #pragma unroll
    for (int a = 0; a < 8; a++) {
        int row = row0 + r0 + a;
        if (row < n_nodes) {
            long long base = (long long)row * D_DIM + c0;
            float4 x0 = *(const float4*)&x[base];
            float4 x1 = *(const float4*)&x[base + 4];
            float4 o0, o1;
            o0.x = fmaxf(acc[a][0], 0.f) + x0.x;
            o0.y = fmaxf(acc[a][1], 0.f) + x0.y;
            o0.z = fmaxf(acc[a][2], 0.f) + x0.z;
            o0.w = fmaxf(acc[a][3], 0.f) + x0.w;
            o1.x = fmaxf(acc[a][4], 0.f) + x1.x;
            o1.y = fmaxf(acc[a][5], 0.f) + x1.y;
            o1.z = fmaxf(acc[a][6], 0.f) + x1.z;
            o1.w = fmaxf(acc[a][7], 0.f) + x1.w;
            *(float4*)&out[base] = o0;
            *(float4*)&out[base + 4] = o1;
        }
    }
}

// ---------------------------------------------------------------------------
extern "C" void kernel_launch(void* const* d_in, const int* in_sizes, int n_in,
                              void* d_out, int out_size) {
    const float* x   = (const float*)d_in[0];
    const void*  src = d_in[1];
    const void*  dst = d_in[2];
    const float* W   = (const float*)d_in[3];
    float* out = (float*)d_out;

    int n_nodes = in_sizes[0] / D_DIM;
    int n_edges = in_sizes[1];

    static const size_t smem_bytes =
        (D_DIM * D_DIM + D_DIM * AS_STRIDE) * sizeof(float);   // ~130KB
    cudaFuncSetAttribute(gemm_kernel, cudaFuncAttributeMaxDynamicSharedMemorySize,
                         (int)smem_bytes);

    int eblocks = (n_edges + 255) / 256;

    // 1. Index dtype detection + count zeroing + W transpose (all tiny).
    detect_kernel<<<1, 64>>>(src, n_edges, n_nodes);
    zero_count_kernel<<<(n_nodes + 255) / 256, 256>>>(n_nodes);
    transpose_W_kernel<<<dim3(4, 4), dim3(32, 8)>>>(W);

    // 2. CSR build: histogram -> scan -> placement.
    hist_kernel<<<eblocks, 256>>>(dst, n_edges);
    scan_kernel<<<1, SCAN_THREADS>>>(n_nodes);
    place_kernel<<<eblocks, 256>>>(src, dst, n_edges);

    // 3. Atomic-free gather (one warp per node).
    {
        int warps_per_block = 8;
        int blocks = (n_nodes + warps_per_block - 1) / warps_per_block;
        gather_kernel<<<blocks, warps_per_block * 32>>>(x, n_nodes);
    }

    // 4. GEMM + ReLU + residual.
    {
        int blocks = (n_nodes + 127) / 128;
        gemm_kernel<<<blocks, 256, smem_bytes>>>(x, out, n_nodes);
    }
}

// round 6
// speedup vs baseline: 1.3408x; 1.3408x over previous
#include <cuda_runtime.h>
#include <cuda_bf16.h>

#define D_DIM 128
#define MAX_NODES 50000
#define AS_STRIDE 132
#define EPW 4   // edges per warp in scatter

__device__ float g_agg[MAX_NODES * D_DIM];
__device__ float g_Wt[D_DIM * D_DIM];   // Wt[k][j] = W[j][k]
__device__ int g_idx64;

// ---------------------------------------------------------------------------
// Detect int64 vs int32 indices (JAX without x64 silently emits i32).
// ---------------------------------------------------------------------------
__global__ void detect_kernel(const void* srcp, int n_edges, int n_nodes) {
    if (threadIdx.x == 0) g_idx64 = 1;
    __syncthreads();
    int n = n_edges < 64 ? n_edges : 64;
    if (threadIdx.x < n) {
        long long v = ((const long long*)srcp)[threadIdx.x];
        if (v < 0 || v >= (long long)n_nodes) g_idx64 = 0;
    }
}

// ---------------------------------------------------------------------------
// Zero the aggregation buffer (vectorized).
// ---------------------------------------------------------------------------
__global__ void zero_kernel(int n_float4) {
    int i = blockIdx.x * blockDim.x + threadIdx.x;
    float4 z = make_float4(0.f, 0.f, 0.f, 0.f);
    float4* p = (float4*)g_agg;
    for (; i < n_float4; i += gridDim.x * blockDim.x) p[i] = z;
}

// ---------------------------------------------------------------------------
// Transpose W [j][k] -> g_Wt [k][j] (32x33 smem tile). grid (4,4), block (32,8).
// ---------------------------------------------------------------------------
__global__ void transpose_W_kernel(const float* __restrict__ W) {
    __shared__ float t[32][33];
    int x = blockIdx.x * 32 + threadIdx.x;
    #pragma unroll
    for (int i = threadIdx.y; i < 32; i += 8)
        t[i][threadIdx.x] = W[(blockIdx.y * 32 + i) * D_DIM + x];
    __syncthreads();
    int xo = blockIdx.y * 32 + threadIdx.x;
    #pragma unroll
    for (int i = threadIdx.y; i < 32; i += 8)
        g_Wt[(blockIdx.x * 32 + i) * D_DIM + xo] = t[threadIdx.x][i];
}

// ---------------------------------------------------------------------------
// Scatter v2: EPW=4 edges per warp. All 4 coalesced 512B gathers are issued
// back-to-back (MLP=4 per warp, vs 1 in v1), then 4 fire-and-forget
// red.global.add.v4.f32. Targets the LTS throughput cap instead of being
// L2-latency-limited.
// ---------------------------------------------------------------------------
__global__ void scatter_kernel(const float* __restrict__ x,
                               const void* __restrict__ srcp,
                               const void* __restrict__ dstp,
                               int n_edges) {
    int warps_per_block = blockDim.x >> 5;
    int warp_id = blockIdx.x * warps_per_block + (threadIdx.x >> 5);
    int e0 = warp_id * EPW;
    if (e0 >= n_edges) return;
    int lane = threadIdx.x & 31;
    bool full = (e0 + EPW <= n_edges);

    long long s[EPW], d[EPW];
    if (g_idx64) {
        const long long* sp = (const long long*)srcp;
        const long long* dp = (const long long*)dstp;
        #pragma unroll
        for (int j = 0; j < EPW; j++) {
            int e = full ? (e0 + j) : min(e0 + j, n_edges - 1);
            s[j] = sp[e]; d[j] = dp[e];
        }
    } else {
        const int* sp = (const int*)srcp;
        const int* dp = (const int*)dstp;
        #pragma unroll
        for (int j = 0; j < EPW; j++) {
            int e = full ? (e0 + j) : min(e0 + j, n_edges - 1);
            s[j] = sp[e]; d[j] = dp[e];
        }
    }

    // Issue all gathers first: independent LDG.128s in flight together.
    float4 v[EPW];
    #pragma unroll
    for (int j = 0; j < EPW; j++)
        v[j] = ((const float4*)(x + s[j] * D_DIM))[lane];

    #pragma unroll
    for (int j = 0; j < EPW; j++) {
        if (full || e0 + j < n_edges) {
            float* outp = g_agg + d[j] * D_DIM + lane * 4;
            asm volatile("red.global.add.v4.f32 [%0], {%1,%2,%3,%4};"
                         :: "l"(outp), "f"(v[j].x), "f"(v[j].y),
                            "f"(v[j].z), "f"(v[j].w)
                         : "memory");
        }
    }
}

// ---------------------------------------------------------------------------
// GEMM + ReLU + residual. 128x128 block tile, 256 threads, 8x8 per thread.
// Smem: Ws (64KB) + As (padded, ~67KB); 1 CTA/SM; 1 B/FMA from smem.
// ---------------------------------------------------------------------------
__global__ __launch_bounds__(256, 1)
void gemm_kernel(const float* __restrict__ x,
                 float* __restrict__ out,
                 int n_nodes) {
    extern __shared__ float smem[];
    float* Ws = smem;                    // [128][128]
    float* As = smem + D_DIM * D_DIM;    // [128][AS_STRIDE]

    int tid = threadIdx.x;
    int row0 = blockIdx.x * 128;

    #pragma unroll
    for (int i = tid; i < D_DIM * D_DIM; i += 256)
        Ws[i] = g_Wt[i];

    #pragma unroll
    for (int i = tid; i < 128 * D_DIM; i += 256) {
        int r = i >> 7;
        int k = i & 127;
        int row = row0 + r;
        float v = (row < n_nodes) ? g_agg[(long long)row * D_DIM + k] : 0.f;
        As[k * AS_STRIDE + r] = v;
    }
    __syncthreads();

    int tx = tid & 15;
    int ty = tid >> 4;
    int r0 = ty * 8;
    int c0 = tx * 8;

    float acc[8][8];
    #pragma unroll
    for (int a = 0; a < 8; a++)
        #pragma unroll
        for (int b = 0; b < 8; b++) acc[a][b] = 0.f;

    #pragma unroll 4
    for (int k = 0; k < D_DIM; k++) {
        float4 a0 = *(const float4*)&As[k * AS_STRIDE + r0];
        float4 a1 = *(const float4*)&As[k * AS_STRIDE + r0 + 4];
        float4 w0 = *(const float4*)&Ws[k * D_DIM + c0];
        float4 w1 = *(const float4*)&Ws[k * D_DIM + c0 + 4];
        float av[8] = {a0.x, a0.y, a0.z, a0.w, a1.x, a1.y, a1.z, a1.w};
        float wv[8] = {w0.x, w0.y, w0.z, w0.w, w1.x, w1.y, w1.z, w1.w};
        #pragma unroll
        for (int a = 0; a < 8; a++)
            #pragma unroll
            for (int b = 0; b < 8; b++)
                acc[a][b] = fmaf(av[a], wv[b], acc[a][b]);
    }

    #pragma unroll
    for (int a = 0; a < 8; a++) {
        int row = row0 + r0 + a;
        if (row < n_nodes) {
            long long base = (long long)row * D_DIM + c0;
            float4 x0 = *(const float4*)&x[base];
            float4 x1 = *(const float4*)&x[base + 4];
            float4 o0, o1;
            o0.x = fmaxf(acc[a][0], 0.f) + x0.x;
            o0.y = fmaxf(acc[a][1], 0.f) + x0.y;
            o0.z = fmaxf(acc[a][2], 0.f) + x0.z;
            o0.w = fmaxf(acc[a][3], 0.f) + x0.w;
            o1.x = fmaxf(acc[a][4], 0.f) + x1.x;
            o1.y = fmaxf(acc[a][5], 0.f) + x1.y;
            o1.z = fmaxf(acc[a][6], 0.f) + x1.z;
            o1.w = fmaxf(acc[a][7], 0.f) + x1.w;
            *(float4*)&out[base] = o0;
            *(float4*)&out[base + 4] = o1;
        }
    }
}

// ---------------------------------------------------------------------------
extern "C" void kernel_launch(void* const* d_in, const int* in_sizes, int n_in,
                              void* d_out, int out_size) {
    const float* x   = (const float*)d_in[0];
    const void*  src = d_in[1];
    const void*  dst = d_in[2];
    const float* W   = (const float*)d_in[3];
    float* out = (float*)d_out;

    int n_nodes = in_sizes[0] / D_DIM;
    int n_edges = in_sizes[1];

    static const size_t smem_bytes =
        (D_DIM * D_DIM + D_DIM * AS_STRIDE) * sizeof(float);   // ~130KB
    cudaFuncSetAttribute(gemm_kernel, cudaFuncAttributeMaxDynamicSharedMemorySize,
                         (int)smem_bytes);

    // 1. Detect index dtype.
    detect_kernel<<<1, 64>>>(src, n_edges, n_nodes);

    // 2. Zero aggregation buffer; transpose W (tiny, independent).
    int n_f4 = n_nodes * D_DIM / 4;
    zero_kernel<<<1024, 256>>>(n_f4);
    transpose_W_kernel<<<dim3(4, 4), dim3(32, 8)>>>(W);

    // 3. Edge scatter: 4 edges per warp, batched gathers.
    {
        int warps_per_block = 8;            // 256 threads
        int edges_per_block = warps_per_block * EPW;
        int blocks = (n_edges + edges_per_block - 1) / edges_per_block;
        scatter_kernel<<<blocks, warps_per_block * 32>>>(x, src, dst, n_edges);
    }

    // 4. GEMM + ReLU + residual.
    {
        int blocks = (n_nodes + 127) / 128;
        gemm_kernel<<<blocks, 256, smem_bytes>>>(x, out, n_nodes);
    }
}

// round 9
// speedup vs baseline: 1.7582x; 1.3113x over previous
#include <cuda_runtime.h>
#include <cuda_bf16.h>
#include <cstdint>

#define D_DIM 128
#define MAX_NODES 50000
#define EPW 8          // edges per warp in scatter
#define SMS 132        // padded smem row stride (floats) for tf32 gemm tiles

__device__ float g_agg[MAX_NODES * D_DIM];
__device__ int g_idx64;

// ---------------------------------------------------------------------------
// Detect int64 vs int32 indices (JAX without x64 silently emits i32).
// ---------------------------------------------------------------------------
__global__ void detect_kernel(const void* srcp, int n_edges, int n_nodes) {
    if (threadIdx.x == 0) g_idx64 = 1;
    __syncthreads();
    int n = n_edges < 64 ? n_edges : 64;
    if (threadIdx.x < n) {
        long long v = ((const long long*)srcp)[threadIdx.x];
        if (v < 0 || v >= (long long)n_nodes) g_idx64 = 0;
    }
}

// ---------------------------------------------------------------------------
// Zero the aggregation buffer (vectorized).
// ---------------------------------------------------------------------------
__global__ void zero_kernel(int n_float4) {
    int i = blockIdx.x * blockDim.x + threadIdx.x;
    float4 z = make_float4(0.f, 0.f, 0.f, 0.f);
    float4* p = (float4*)g_agg;
    for (; i < n_float4; i += gridDim.x * blockDim.x) p[i] = z;
}

// ---------------------------------------------------------------------------
// Scatter: EPW edges per warp, all gathers issued back-to-back (MLP=EPW),
// then fire-and-forget red.global.add.v4.f32.
// ---------------------------------------------------------------------------
__global__ void scatter_kernel(const float* __restrict__ x,
                               const void* __restrict__ srcp,
                               const void* __restrict__ dstp,
                               int n_edges) {
    int warps_per_block = blockDim.x >> 5;
    int warp_id = blockIdx.x * warps_per_block + (threadIdx.x >> 5);
    int e0 = warp_id * EPW;
    if (e0 >= n_edges) return;
    int lane = threadIdx.x & 31;
    bool full = (e0 + EPW <= n_edges);

    int s[EPW], d[EPW];
    if (g_idx64) {
        const long long* sp = (const long long*)srcp;
        const long long* dp = (const long long*)dstp;
        #pragma unroll
        for (int j = 0; j < EPW; j++) {
            int e = full ? (e0 + j) : min(e0 + j, n_edges - 1);
            s[j] = (int)sp[e]; d[j] = (int)dp[e];
        }
    } else {
        const int* sp = (const int*)srcp;
        const int* dp = (const int*)dstp;
        #pragma unroll
        for (int j = 0; j < EPW; j++) {
            int e = full ? (e0 + j) : min(e0 + j, n_edges - 1);
            s[j] = sp[e]; d[j] = dp[e];
        }
    }

    float4 v[EPW];
    #pragma unroll
    for (int j = 0; j < EPW; j++)
        v[j] = ((const float4*)(x + (long long)s[j] * D_DIM))[lane];

    #pragma unroll
    for (int j = 0; j < EPW; j++) {
        if (full || e0 + j < n_edges) {
            float* outp = g_agg + (long long)d[j] * D_DIM + lane * 4;
            asm volatile("red.global.add.v4.f32 [%0], {%1,%2,%3,%4};"
                         :: "l"(outp), "f"(v[j].x), "f"(v[j].y),
                            "f"(v[j].z), "f"(v[j].w)
                         : "memory");
        }
    }
}

// ---------------------------------------------------------------------------
// tf32 tensor-core GEMM + ReLU + residual:
//   out[n][j] = relu( sum_k agg[n][k] * W[j][k] ) + x[n][j]
// mma.sync.m16n8k8.row.col: A = agg tile (row-major [n][k]),
// B = W directly (col-major KxN == W[j][k] row-major). No W transpose needed.
// Block: 256 threads (8 warps as 2x4), tile 128x128, warp tile 64x32.
// Smem tiles padded to stride 132 -> fragment LDS.32 reads conflict-free
// (bank = (132*g + tig) % 32 covers all 32 banks).
// Inputs rounded to tf32 once during smem fill; fp32 accumulation.
// ---------------------------------------------------------------------------
__global__ __launch_bounds__(256, 1)
void gemm_tf32_kernel(const float* __restrict__ x,
                      const float* __restrict__ W,
                      float* __restrict__ out,
                      int n_nodes) {
    extern __shared__ float smem[];
    float* As = smem;              // [128][SMS]  agg rows
    float* Bs = smem + 128 * SMS;  // [128][SMS]  W rows (j-major)

    int tid = threadIdx.x;
    int row0 = blockIdx.x * 128;

    // Fill As (agg tile) and Bs (full W), rounding to tf32.
    #pragma unroll
    for (int i = tid; i < 128 * (D_DIM / 4); i += 256) {
        int r = i >> 5;            // 32 float4 per row
        int k = (i & 31) * 4;
        int row = row0 + r;
        float4 a = (row < n_nodes)
            ? *(const float4*)&g_agg[(long long)row * D_DIM + k]
            : make_float4(0.f, 0.f, 0.f, 0.f);
        float4 b = *(const float4*)&W[r * D_DIM + k];
        uint32_t t;
        asm("cvt.rna.tf32.f32 %0, %1;" : "=r"(t) : "f"(a.x)); a.x = __uint_as_float(t);
        asm("cvt.rna.tf32.f32 %0, %1;" : "=r"(t) : "f"(a.y)); a.y = __uint_as_float(t);
        asm("cvt.rna.tf32.f32 %0, %1;" : "=r"(t) : "f"(a.z)); a.z = __uint_as_float(t);
        asm("cvt.rna.tf32.f32 %0, %1;" : "=r"(t) : "f"(a.w)); a.w = __uint_as_float(t);
        asm("cvt.rna.tf32.f32 %0, %1;" : "=r"(t) : "f"(b.x)); b.x = __uint_as_float(t);
        asm("cvt.rna.tf32.f32 %0, %1;" : "=r"(t) : "f"(b.y)); b.y = __uint_as_float(t);
        asm("cvt.rna.tf32.f32 %0, %1;" : "=r"(t) : "f"(b.z)); b.z = __uint_as_float(t);
        asm("cvt.rna.tf32.f32 %0, %1;" : "=r"(t) : "f"(b.w)); b.w = __uint_as_float(t);
        *(float4*)&As[r * SMS + k] = a;
        *(float4*)&Bs[r * SMS + k] = b;
    }
    __syncthreads();

    int warp = tid >> 5;
    int lane = tid & 31;
    int g   = lane >> 2;     // groupID 0..7
    int tig = lane & 3;      // thread-in-group 0..3
    int wm = warp >> 2;      // 0..1 -> 64-row slab
    int wn = warp & 3;       // 0..3 -> 32-col slab
    int wr = wm * 64;
    int wc = wn * 32;

    float acc[4][4][4];      // [m-frag][n-frag][c0..c3]
    #pragma unroll
    for (int mi = 0; mi < 4; mi++)
        #pragma unroll
        for (int ni = 0; ni < 4; ni++)
            #pragma unroll
            for (int c = 0; c < 4; c++) acc[mi][ni][c] = 0.f;

    #pragma unroll 2
    for (int k0 = 0; k0 < D_DIM; k0 += 8) {
        uint32_t a[4][4], b[4][2];
        #pragma unroll
        for (int mi = 0; mi < 4; mi++) {
            const float* base = &As[(wr + mi * 16 + g) * SMS + k0 + tig];
            a[mi][0] = __float_as_uint(base[0]);
            a[mi][1] = __float_as_uint(base[8 * SMS]);
            a[mi][2] = __float_as_uint(base[4]);
            a[mi][3] = __float_as_uint(base[8 * SMS + 4]);
        }
        #pragma unroll
        for (int ni = 0; ni < 4; ni++) {
            const float* base = &Bs[(wc + ni * 8 + g) * SMS + k0 + tig];
            b[ni][0] = __float_as_uint(base[0]);
            b[ni][1] = __float_as_uint(base[4]);
        }
        #pragma unroll
        for (int mi = 0; mi < 4; mi++)
            #pragma unroll
            for (int ni = 0; ni < 4; ni++) {
                asm volatile(
                    "mma.sync.aligned.m16n8k8.row.col.f32.tf32.tf32.f32 "
                    "{%0,%1,%2,%3}, {%4,%5,%6,%7}, {%8,%9}, {%0,%1,%2,%3};"
                    : "+f"(acc[mi][ni][0]), "+f"(acc[mi][ni][1]),
                      "+f"(acc[mi][ni][2]), "+f"(acc[mi][ni][3])
                    : "r"(a[mi][0]), "r"(a[mi][1]), "r"(a[mi][2]), "r"(a[mi][3]),
                      "r"(b[ni][0]), "r"(b[ni][1]));
            }
    }

    // Epilogue: relu + residual. c0/c1 -> (row, col..col+1), c2/c3 -> row+8.
    #pragma unroll
    for (int mi = 0; mi < 4; mi++) {
        #pragma unroll
        for (int half = 0; half < 2; half++) {
            int row = row0 + wr + mi * 16 + g + half * 8;
            if (row < n_nodes) {
                #pragma unroll
                for (int ni = 0; ni < 4; ni++) {
                    int col = wc + ni * 8 + tig * 2;
                    long long base = (long long)row * D_DIM + col;
                    float2 xr = *(const float2*)&x[base];
                    float2 o;
                    o.x = fmaxf(acc[mi][ni][half * 2 + 0], 0.f) + xr.x;
                    o.y = fmaxf(acc[mi][ni][half * 2 + 1], 0.f) + xr.y;
                    *(float2*)&out[base] = o;
                }
            }
        }
    }
}

// ---------------------------------------------------------------------------
extern "C" void kernel_launch(void* const* d_in, const int* in_sizes, int n_in,
                              void* d_out, int out_size) {
    const float* x   = (const float*)d_in[0];
    const void*  src = d_in[1];
    const void*  dst = d_in[2];
    const float* W   = (const float*)d_in[3];
    float* out = (float*)d_out;

    int n_nodes = in_sizes[0] / D_DIM;
    int n_edges = in_sizes[1];

    static const size_t smem_bytes = 2 * 128 * SMS * sizeof(float);  // ~132KB
    cudaFuncSetAttribute(gemm_tf32_kernel,
                         cudaFuncAttributeMaxDynamicSharedMemorySize,
                         (int)smem_bytes);

    // 1. Detect index dtype.
    detect_kernel<<<1, 64>>>(src, n_edges, n_nodes);

    // 2. Zero aggregation buffer.
    int n_f4 = n_nodes * D_DIM / 4;
    zero_kernel<<<1024, 256>>>(n_f4);

    // 3. Edge scatter: EPW edges per warp, batched gathers.
    {
        int warps_per_block = 8;            // 256 threads
        int edges_per_block = warps_per_block * EPW;
        int blocks = (n_edges + edges_per_block - 1) / edges_per_block;
        scatter_kernel<<<blocks, warps_per_block * 32>>>(x, src, dst, n_edges);
    }

    // 4. tf32 tensor GEMM + ReLU + residual.
    {
        int blocks = (n_nodes + 127) / 128;
        gemm_tf32_kernel<<<blocks, 256, smem_bytes>>>(x, W, out, n_nodes);
    }
}

// round 10
// speedup vs baseline: 1.7659x; 1.0044x over previous
#include <cuda_runtime.h>
#include <cuda_bf16.h>
#include <cstdint>

#define D_DIM 128
#define MAX_NODES 50000
#define EPW 8          // edges per warp in scatter
#define SMS 132        // padded smem row stride (floats)
#define TROWS 64       // A-tile rows per block (2 CTAs/SM)

__device__ float g_agg[MAX_NODES * D_DIM];
__device__ int g_idx64;

// ---------------------------------------------------------------------------
// Detect int64 vs int32 indices (JAX without x64 silently emits i32).
// ---------------------------------------------------------------------------
__global__ void detect_kernel(const void* srcp, int n_edges, int n_nodes) {
    if (threadIdx.x == 0) g_idx64 = 1;
    __syncthreads();
    int n = n_edges < 64 ? n_edges : 64;
    if (threadIdx.x < n) {
        long long v = ((const long long*)srcp)[threadIdx.x];
        if (v < 0 || v >= (long long)n_nodes) g_idx64 = 0;
    }
}

// ---------------------------------------------------------------------------
// Zero the aggregation buffer (vectorized).
// ---------------------------------------------------------------------------
__global__ void zero_kernel(int n_float4) {
    int i = blockIdx.x * blockDim.x + threadIdx.x;
    float4 z = make_float4(0.f, 0.f, 0.f, 0.f);
    float4* p = (float4*)g_agg;
    for (; i < n_float4; i += gridDim.x * blockDim.x) p[i] = z;
}

// ---------------------------------------------------------------------------
// Scatter: EPW edges per warp, all gathers issued back-to-back (MLP=EPW),
// then fire-and-forget red.global.add.v4.f32. Near the LTS traffic floor.
// ---------------------------------------------------------------------------
__global__ void scatter_kernel(const float* __restrict__ x,
                               const void* __restrict__ srcp,
                               const void* __restrict__ dstp,
                               int n_edges) {
    int warps_per_block = blockDim.x >> 5;
    int warp_id = blockIdx.x * warps_per_block + (threadIdx.x >> 5);
    int e0 = warp_id * EPW;
    if (e0 >= n_edges) return;
    int lane = threadIdx.x & 31;
    bool full = (e0 + EPW <= n_edges);

    int s[EPW], d[EPW];
    if (g_idx64) {
        const long long* sp = (const long long*)srcp;
        const long long* dp = (const long long*)dstp;
        #pragma unroll
        for (int j = 0; j < EPW; j++) {
            int e = full ? (e0 + j) : min(e0 + j, n_edges - 1);
            s[j] = (int)sp[e]; d[j] = (int)dp[e];
        }
    } else {
        const int* sp = (const int*)srcp;
        const int* dp = (const int*)dstp;
        #pragma unroll
        for (int j = 0; j < EPW; j++) {
            int e = full ? (e0 + j) : min(e0 + j, n_edges - 1);
            s[j] = sp[e]; d[j] = dp[e];
        }
    }

    float4 v[EPW];
    #pragma unroll
    for (int j = 0; j < EPW; j++)
        v[j] = ((const float4*)(x + (long long)s[j] * D_DIM))[lane];

    #pragma unroll
    for (int j = 0; j < EPW; j++) {
        if (full || e0 + j < n_edges) {
            float* outp = g_agg + (long long)d[j] * D_DIM + lane * 4;
            asm volatile("red.global.add.v4.f32 [%0], {%1,%2,%3,%4};"
                         :: "l"(outp), "f"(v[j].x), "f"(v[j].y),
                            "f"(v[j].z), "f"(v[j].w)
                         : "memory");
        }
    }
}

// ---------------------------------------------------------------------------
// tf32 tensor-core GEMM + ReLU + residual:
//   out[n][j] = relu( sum_k agg[n][k] * W[j][k] ) + x[n][j]
// mma.sync.m16n8k8.row.col; B = W in native [j][k] layout.
// Block: 256 threads (8 warps as 2x4), tile TROWS(64) x 128, warp tile 32x32.
// Smem: As 64x132 + Bs 128x132 = ~101KB -> 2 CTAs/SM (occupancy doubled vs
// the 128-row variant; fill latency of one CTA hides under the other's
// mainloop). Fragment LDS reads conflict-free via stride-132 padding.
// ---------------------------------------------------------------------------
__global__ __launch_bounds__(256, 2)
void gemm_tf32_kernel(const float* __restrict__ x,
                      const float* __restrict__ W,
                      float* __restrict__ out,
                      int n_nodes) {
    extern __shared__ float smem[];
    float* As = smem;                // [TROWS][SMS]
    float* Bs = smem + TROWS * SMS;  // [128][SMS]

    int tid = threadIdx.x;
    int row0 = blockIdx.x * TROWS;

    // Fill Bs (full W) rounding to tf32: 128 rows.
    #pragma unroll
    for (int i = tid; i < 128 * (D_DIM / 4); i += 256) {
        int r = i >> 5;
        int k = (i & 31) * 4;
        float4 b = *(const float4*)&W[r * D_DIM + k];
        uint32_t t;
        asm("cvt.rna.tf32.f32 %0, %1;" : "=r"(t) : "f"(b.x)); b.x = __uint_as_float(t);
        asm("cvt.rna.tf32.f32 %0, %1;" : "=r"(t) : "f"(b.y)); b.y = __uint_as_float(t);
        asm("cvt.rna.tf32.f32 %0, %1;" : "=r"(t) : "f"(b.z)); b.z = __uint_as_float(t);
        asm("cvt.rna.tf32.f32 %0, %1;" : "=r"(t) : "f"(b.w)); b.w = __uint_as_float(t);
        *(float4*)&Bs[r * SMS + k] = b;
    }
    // Fill As (agg tile, TROWS rows) rounding to tf32.
    #pragma unroll
    for (int i = tid; i < TROWS * (D_DIM / 4); i += 256) {
        int r = i >> 5;
        int k = (i & 31) * 4;
        int row = row0 + r;
        float4 a = (row < n_nodes)
            ? *(const float4*)&g_agg[(long long)row * D_DIM + k]
            : make_float4(0.f, 0.f, 0.f, 0.f);
        uint32_t t;
        asm("cvt.rna.tf32.f32 %0, %1;" : "=r"(t) : "f"(a.x)); a.x = __uint_as_float(t);
        asm("cvt.rna.tf32.f32 %0, %1;" : "=r"(t) : "f"(a.y)); a.y = __uint_as_float(t);
        asm("cvt.rna.tf32.f32 %0, %1;" : "=r"(t) : "f"(a.z)); a.z = __uint_as_float(t);
        asm("cvt.rna.tf32.f32 %0, %1;" : "=r"(t) : "f"(a.w)); a.w = __uint_as_float(t);
        *(float4*)&As[r * SMS + k] = a;
    }
    __syncthreads();

    int warp = tid >> 5;
    int lane = tid & 31;
    int g   = lane >> 2;     // 0..7
    int tig = lane & 3;      // 0..3
    int wr = (warp >> 2) * 32;   // 0 or 32
    int wc = (warp & 3) * 32;    // 0,32,64,96

    float acc[2][4][4];
    #pragma unroll
    for (int mi = 0; mi < 2; mi++)
        #pragma unroll
        for (int ni = 0; ni < 4; ni++)
            #pragma unroll
            for (int c = 0; c < 4; c++) acc[mi][ni][c] = 0.f;

    #pragma unroll 4
    for (int k0 = 0; k0 < D_DIM; k0 += 8) {
        uint32_t a[2][4], b[4][2];
        #pragma unroll
        for (int mi = 0; mi < 2; mi++) {
            const float* base = &As[(wr + mi * 16 + g) * SMS + k0 + tig];
            a[mi][0] = __float_as_uint(base[0]);
            a[mi][1] = __float_as_uint(base[8 * SMS]);
            a[mi][2] = __float_as_uint(base[4]);
            a[mi][3] = __float_as_uint(base[8 * SMS + 4]);
        }
        #pragma unroll
        for (int ni = 0; ni < 4; ni++) {
            const float* base = &Bs[(wc + ni * 8 + g) * SMS + k0 + tig];
            b[ni][0] = __float_as_uint(base[0]);
            b[ni][1] = __float_as_uint(base[4]);
        }
        #pragma unroll
        for (int mi = 0; mi < 2; mi++)
            #pragma unroll
            for (int ni = 0; ni < 4; ni++) {
                asm volatile(
                    "mma.sync.aligned.m16n8k8.row.col.f32.tf32.tf32.f32 "
                    "{%0,%1,%2,%3}, {%4,%5,%6,%7}, {%8,%9}, {%0,%1,%2,%3};"
                    : "+f"(acc[mi][ni][0]), "+f"(acc[mi][ni][1]),
                      "+f"(acc[mi][ni][2]), "+f"(acc[mi][ni][3])
                    : "r"(a[mi][0]), "r"(a[mi][1]), "r"(a[mi][2]), "r"(a[mi][3]),
                      "r"(b[ni][0]), "r"(b[ni][1]));
            }
    }

    // Epilogue: relu + residual.
    #pragma unroll
    for (int mi = 0; mi < 2; mi++) {
        #pragma unroll
        for (int half = 0; half < 2; half++) {
            int row = row0 + wr + mi * 16 + g + half * 8;
            if (row < n_nodes) {
                #pragma unroll
                for (int ni = 0; ni < 4; ni++) {
                    int col = wc + ni * 8 + tig * 2;
                    long long base = (long long)row * D_DIM + col;
                    float2 xr = *(const float2*)&x[base];
                    float2 o;
                    o.x = fmaxf(acc[mi][ni][half * 2 + 0], 0.f) + xr.x;
                    o.y = fmaxf(acc[mi][ni][half * 2 + 1], 0.f) + xr.y;
                    *(float2*)&out[base] = o;
                }
            }
        }
    }
}

// ---------------------------------------------------------------------------
extern "C" void kernel_launch(void* const* d_in, const int* in_sizes, int n_in,
                              void* d_out, int out_size) {
    const float* x   = (const float*)d_in[0];
    const void*  src = d_in[1];
    const void*  dst = d_in[2];
    const float* W   = (const float*)d_in[3];
    float* out = (float*)d_out;

    int n_nodes = in_sizes[0] / D_DIM;
    int n_edges = in_sizes[1];

    static const size_t smem_bytes = (TROWS + 128) * SMS * sizeof(float); // ~101KB
    cudaFuncSetAttribute(gemm_tf32_kernel,
                         cudaFuncAttributeMaxDynamicSharedMemorySize,
                         (int)smem_bytes);

    // 1. Detect index dtype.
    detect_kernel<<<1, 64>>>(src, n_edges, n_nodes);

    // 2. Zero aggregation buffer.
    int n_f4 = n_nodes * D_DIM / 4;
    zero_kernel<<<1024, 256>>>(n_f4);

    // 3. Edge scatter: EPW edges per warp, batched gathers.
    {
        int warps_per_block = 8;            // 256 threads
        int edges_per_block = warps_per_block * EPW;
        int blocks = (n_edges + edges_per_block - 1) / edges_per_block;
        scatter_kernel<<<blocks, warps_per_block * 32>>>(x, src, dst, n_edges);
    }

    // 4. tf32 tensor GEMM + ReLU + residual (64-row tiles, 2 CTAs/SM).
    {
        int blocks = (n_nodes + TROWS - 1) / TROWS;
        gemm_tf32_kernel<<<blocks, 256, smem_bytes>>>(x, W, out, n_nodes);
    }
}